// round 12
// baseline (speedup 1.0000x reference)
#include <cuda_runtime.h>
#include <math.h>

#define N_NODES 100000
#define N_EDGES 3200000
#define SCAN_B 1024
#define SCAN_G 98            // 98*1024 = 100352 >= N_NODES

typedef unsigned long long u64;

// ---------------- scratch (__device__ globals; no allocs) ----------------
__device__ int   g_deg[N_NODES];
__device__ float g_dinv[N_NODES];
__device__ int   g_rowptr[N_NODES + 1];
__device__ int   g_cursor[N_NODES];
__device__ int   g_scan[SCAN_G * SCAN_B];
__device__ int   g_bsum[SCAN_G];
__device__ int   g_boff[SCAN_G];
__device__ int2  g_cw[N_EDGES];           // packed (col, w-bits)
__device__ float g_h0[N_NODES * 16];      // x @ W1
__device__ float g_r1[N_NODES * 16];      // relu(spmm1 + b1)
__device__ float g_t [N_NODES * 16];      // spmm2(r1)

// ---------------- packed f32x2 helpers ----------------
__device__ __forceinline__ u64 pack2(float lo, float hi) {
    u64 r;
    asm("mov.b64 %0, {%1, %2};" : "=l"(r) : "r"(__float_as_uint(lo)), "r"(__float_as_uint(hi)));
    return r;
}
__device__ __forceinline__ u64 dup2(float a) {
    u64 r;
    asm("mov.b64 %0, {%1, %1};" : "=l"(r) : "r"(__float_as_uint(a)));
    return r;
}
__device__ __forceinline__ void ffma2(u64& d, u64 a, u64 b) {
    asm("fma.rn.f32x2 %0, %1, %2, %3;" : "=l"(d) : "l"(a), "l"(b), "l"(d));
}
__device__ __forceinline__ u64 mul2(u64 a, u64 b) {
    u64 r;
    asm("mul.rn.f32x2 %0, %1, %2;" : "=l"(r) : "l"(a), "l"(b));
    return r;
}
__device__ __forceinline__ void unpack2(u64 v, float& lo, float& hi) {
    unsigned int l, h;
    asm("mov.b64 {%0, %1}, %2;" : "=r"(l), "=r"(h) : "l"(v));
    lo = __uint_as_float(l);
    hi = __uint_as_float(h);
}

// ---------------- degree / dinv ----------------
__global__ void k_zero_deg() {
    int i = blockIdx.x * blockDim.x + threadIdx.x;
    if (i < N_NODES) g_deg[i] = 0;
}
__global__ void k_count(const int* __restrict__ ei) {
    int i = blockIdx.x * blockDim.x + threadIdx.x;
    if (i < N_EDGES / 4) {
        int4 v = ((const int4*)ei)[i];
        atomicAdd(&g_deg[v.x], 1);
        atomicAdd(&g_deg[v.y], 1);
        atomicAdd(&g_deg[v.z], 1);
        atomicAdd(&g_deg[v.w], 1);
    }
}

// ---------------- scan (CSR rowptr over real-edge counts) ----------------
__global__ void __launch_bounds__(SCAN_B) k_scan1() {
    __shared__ int s[SCAN_B];
    int t = threadIdx.x;
    int i = blockIdx.x * SCAN_B + t;
    s[t] = (i < N_NODES) ? g_deg[i] : 0;
    __syncthreads();
#pragma unroll
    for (int off = 1; off < SCAN_B; off <<= 1) {
        int add = (t >= off) ? s[t - off] : 0;
        __syncthreads();
        s[t] += add;
        __syncthreads();
    }
    g_scan[i] = s[t];
    if (t == SCAN_B - 1) g_bsum[blockIdx.x] = s[t];
}
__global__ void k_scan2() {
    __shared__ int s[128];
    int t = threadIdx.x;
    s[t] = (t < SCAN_G) ? g_bsum[t] : 0;
    __syncthreads();
#pragma unroll
    for (int off = 1; off < 128; off <<= 1) {
        int add = (t >= off) ? s[t - off] : 0;
        __syncthreads();
        s[t] += add;
        __syncthreads();
    }
    if (t < SCAN_G) g_boff[t] = s[t] - g_bsum[t];  // exclusive
}
__global__ void __launch_bounds__(SCAN_B) k_scan3() {   // + dinv fused
    int i = blockIdx.x * SCAN_B + threadIdx.x;
    if (i < N_NODES) {
        int deg = g_deg[i];
        int incl = g_scan[i] + g_boff[blockIdx.x];
        g_rowptr[i + 1] = incl;
        g_cursor[i] = incl - deg;
        g_dinv[i] = rsqrtf((float)(deg + 1));   // +1 self loop
        if (i == 0) g_rowptr[0] = 0;
    }
}

// ---------------- scatter edges into CSR ----------------
__global__ void k_scatter(const int* __restrict__ ei) {
    int i = blockIdx.x * blockDim.x + threadIdx.x;
    if (i >= N_EDGES / 4) return;
    int4 r4 = ((const int4*)ei)[i];
    int4 c4 = ((const int4*)(ei + N_EDGES))[i];
#pragma unroll
    for (int k = 0; k < 4; k++) {
        int r = (k == 0) ? r4.x : (k == 1) ? r4.y : (k == 2) ? r4.z : r4.w;
        int c = (k == 0) ? c4.x : (k == 1) ? c4.y : (k == 2) ? c4.z : c4.w;
        int pos = atomicAdd(&g_cursor[r], 1);
        float w = g_dinv[r] * g_dinv[c];
        g_cw[pos] = make_int2(c, __float_as_int(w));
    }
}

// ---------------- GEMM1: h0 = x @ W1 (100000x512 @ 512x16), f32x2 ----------------
#define G1_ROWS 256
#define G1_KC   32
__global__ void __launch_bounds__(256) k_gemm1(const float* __restrict__ x,
                                               const float* __restrict__ W1) {
    __shared__ float xs[G1_ROWS][G1_KC + 1];   // stride 33: conflict-free
    __shared__ uint4 w1s[G1_KC * 4];           // 32 k x 16 cols (as 4x uint4)
    int tid = threadIdx.x;
    int row0 = blockIdx.x * G1_ROWS;
    int r = row0 + tid;

    u64 acc[8];                                 // col pairs (0,1)..(14,15)
#pragma unroll
    for (int c = 0; c < 8; c++) acc[c] = 0ull;

    int f4 = tid & 7, rbase = tid >> 3;
    for (int s = 0; s < 512 / G1_KC; s++) {
        if (tid < G1_KC * 4) w1s[tid] = ((const uint4*)W1)[s * G1_KC * 4 + tid];
        int rl = rbase;
#pragma unroll
        for (int i = 0; i < 8; i++, rl += 32) {
            int rr = row0 + rl;
            float4 v = make_float4(0.f, 0.f, 0.f, 0.f);
            if (rr < N_NODES) v = ((const float4*)(x + (size_t)rr * 512))[s * 8 + f4];
            xs[rl][f4 * 4 + 0] = v.x;
            xs[rl][f4 * 4 + 1] = v.y;
            xs[rl][f4 * 4 + 2] = v.z;
            xs[rl][f4 * 4 + 3] = v.w;
        }
        __syncthreads();
#pragma unroll
        for (int k = 0; k < G1_KC; k++) {
            u64 a2 = dup2(xs[tid][k]);
#pragma unroll
            for (int c2 = 0; c2 < 4; c2++) {
                uint4 w = w1s[k * 4 + c2];
                u64 wlo, whi;
                asm("mov.b64 %0, {%1, %2};" : "=l"(wlo) : "r"(w.x), "r"(w.y));
                asm("mov.b64 %0, {%1, %2};" : "=l"(whi) : "r"(w.z), "r"(w.w));
                ffma2(acc[c2 * 2 + 0], a2, wlo);
                ffma2(acc[c2 * 2 + 1], a2, whi);
            }
        }
        __syncthreads();
    }
    if (r < N_NODES) {
        ulonglong2* o = (ulonglong2*)(g_h0 + (size_t)r * 16);
#pragma unroll
        for (int i = 0; i < 4; i++)
            o[i] = make_ulonglong2(acc[2 * i], acc[2 * i + 1]);
    }
}

// ---------------- gather SpMM (16-wide): 1 thread per row, f32x2 ----------------
// STAGE 1: g_r1 = relu(spmm(g_h0) + b1);  STAGE 2: g_t = spmm(g_r1)
template <int STAGE>
__global__ void k_gather(const float* __restrict__ bias) {
    const float* __restrict__ src = (STAGE == 1) ? g_h0 : g_r1;
    float* __restrict__       dst = (STAGE == 1) ? g_r1 : g_t;
    int r = blockIdx.x * blockDim.x + threadIdx.x;
    if (r >= N_NODES) return;

    float d = g_dinv[r];
    u64 dd2 = dup2(d * d);
    const ulonglong2* s2 = (const ulonglong2*)src;

    u64 acc[8];
    {   // self-loop init: acc = dd * src[r]
        const ulonglong2* me = s2 + (size_t)r * 4;
#pragma unroll
        for (int i = 0; i < 4; i++) {
            ulonglong2 v = me[i];
            acc[2 * i + 0] = mul2(dd2, v.x);
            acc[2 * i + 1] = mul2(dd2, v.y);
        }
    }

    int e = g_rowptr[r], e1 = g_rowptr[r + 1];
#pragma unroll 2
    for (; e < e1; e++) {
        int2 cw = g_cw[e];
        u64 w2 = dup2(__int_as_float(cw.y));
        const ulonglong2* h = s2 + (size_t)cw.x * 4;
        ulonglong2 h0 = h[0], h1 = h[1], h2 = h[2], h3 = h[3];
        ffma2(acc[0], w2, h0.x);
        ffma2(acc[1], w2, h0.y);
        ffma2(acc[2], w2, h1.x);
        ffma2(acc[3], w2, h1.y);
        ffma2(acc[4], w2, h2.x);
        ffma2(acc[5], w2, h2.y);
        ffma2(acc[6], w2, h3.x);
        ffma2(acc[7], w2, h3.y);
    }

    if (STAGE == 1) {
        float out[16];
#pragma unroll
        for (int i = 0; i < 8; i++) unpack2(acc[i], out[2 * i], out[2 * i + 1]);
#pragma unroll
        for (int j = 0; j < 16; j++) out[j] = fmaxf(out[j] + bias[j], 0.f);
        float4* o = (float4*)(dst + (size_t)r * 16);
#pragma unroll
        for (int j4 = 0; j4 < 4; j4++)
            o[j4] = make_float4(out[j4 * 4], out[j4 * 4 + 1], out[j4 * 4 + 2], out[j4 * 4 + 3]);
    } else {
        ulonglong2* o = (ulonglong2*)(dst + (size_t)r * 16);
#pragma unroll
        for (int i = 0; i < 4; i++)
            o[i] = make_ulonglong2(acc[2 * i], acc[2 * i + 1]);
    }
}

// ---------------- fused GEMM2 + bias + log_softmax ----------------
__global__ void __launch_bounds__(256) k_gemm2lsm(const float* __restrict__ W2,
                                                  const float* __restrict__ b2,
                                                  float* __restrict__ out) {
    __shared__ float4 w2s[160];   // 16 x 40
    __shared__ float  b2s[40];
    for (int i = threadIdx.x; i < 160; i += 256) w2s[i] = ((const float4*)W2)[i];
    if (threadIdx.x < 40) b2s[threadIdx.x] = b2[threadIdx.x];
    __syncthreads();

    int r = blockIdx.x * blockDim.x + threadIdx.x;
    if (r >= N_NODES) return;

    float tv[16];
    const float4* tp = (const float4*)(g_t + (size_t)r * 16);
#pragma unroll
    for (int k4 = 0; k4 < 4; k4++) {
        float4 v = tp[k4];
        tv[k4 * 4 + 0] = v.x; tv[k4 * 4 + 1] = v.y;
        tv[k4 * 4 + 2] = v.z; tv[k4 * 4 + 3] = v.w;
    }

    float acc[40];
#pragma unroll
    for (int j = 0; j < 40; j++) acc[j] = b2s[j];
#pragma unroll
    for (int k = 0; k < 16; k++) {
        float a = tv[k];
#pragma unroll
        for (int j4 = 0; j4 < 10; j4++) {
            float4 w = w2s[k * 10 + j4];
            acc[j4 * 4 + 0] += a * w.x;
            acc[j4 * 4 + 1] += a * w.y;
            acc[j4 * 4 + 2] += a * w.z;
            acc[j4 * 4 + 3] += a * w.w;
        }
    }
    float m = acc[0];
#pragma unroll
    for (int j = 1; j < 40; j++) m = fmaxf(m, acc[j]);
    float s = 0.f;
#pragma unroll
    for (int j = 0; j < 40; j++) s += expf(acc[j] - m);
    float L = m + logf(s);
    float4* o = (float4*)(out + (size_t)r * 40);
#pragma unroll
    for (int j4 = 0; j4 < 10; j4++)
        o[j4] = make_float4(acc[j4 * 4] - L, acc[j4 * 4 + 1] - L,
                            acc[j4 * 4 + 2] - L, acc[j4 * 4 + 3] - L);
}

// ---------------- launch ----------------
extern "C" void kernel_launch(void* const* d_in, const int* in_sizes, int n_in,
                              void* d_out, int out_size) {
    const float* x  = (const float*)d_in[0];
    const float* W1 = (const float*)d_in[1];
    const float* b1 = (const float*)d_in[2];
    const float* W2 = (const float*)d_in[3];
    const float* b2 = (const float*)d_in[4];
    const int*   ei = (const int*)d_in[5];
    float* out = (float*)d_out;

    k_zero_deg<<<(N_NODES + 255) / 256, 256>>>();
    k_count<<<(N_EDGES / 4 + 255) / 256, 256>>>(ei);

    k_scan1<<<SCAN_G, SCAN_B>>>();
    k_scan2<<<1, 128>>>();
    k_scan3<<<SCAN_G, SCAN_B>>>();
    k_scatter<<<(N_EDGES / 4 + 255) / 256, 256>>>(ei);

    k_gemm1<<<(N_NODES + G1_ROWS - 1) / G1_ROWS, 256>>>(x, W1);

    k_gather<1><<<(N_NODES + 255) / 256, 256>>>(b1);
    k_gather<2><<<(N_NODES + 255) / 256, 256>>>(b1);

    k_gemm2lsm<<<(N_NODES + 255) / 256, 256>>>(W2, b2, out);
}

// round 13
// speedup vs baseline: 1.0008x; 1.0008x over previous
#include <cuda_runtime.h>
#include <math.h>

#define N_NODES 100000
#define N_EDGES 3200000
#define SCAN_B 1024
#define SCAN_G 98            // 98*1024 = 100352 >= N_NODES

typedef unsigned long long u64;

// ---------------- scratch (__device__ globals; no allocs) ----------------
__device__ int   g_deg[N_NODES];
__device__ float g_dinv[N_NODES];
__device__ int   g_rowptr[N_NODES + 1];
__device__ int   g_cursor[N_NODES];
__device__ int   g_scan[SCAN_G * SCAN_B];
__device__ int   g_bsum[SCAN_G];
__device__ int   g_boff[SCAN_G];
__device__ int2  g_cw[N_EDGES];           // packed (col, w-bits)
__device__ float g_h0[N_NODES * 16];      // x @ W1
__device__ float g_r1[N_NODES * 16];      // relu(spmm1 + b1)
__device__ float g_t [N_NODES * 16];      // spmm2(r1)

// ---------------- packed f32x2 helpers ----------------
__device__ __forceinline__ u64 pack2(float lo, float hi) {
    u64 r;
    asm("mov.b64 %0, {%1, %2};" : "=l"(r) : "r"(__float_as_uint(lo)), "r"(__float_as_uint(hi)));
    return r;
}
__device__ __forceinline__ u64 dup2(float a) {
    u64 r;
    asm("mov.b64 %0, {%1, %1};" : "=l"(r) : "r"(__float_as_uint(a)));
    return r;
}
__device__ __forceinline__ void ffma2(u64& d, u64 a, u64 b) {
    asm("fma.rn.f32x2 %0, %1, %2, %3;" : "=l"(d) : "l"(a), "l"(b), "l"(d));
}
__device__ __forceinline__ u64 mul2(u64 a, u64 b) {
    u64 r;
    asm("mul.rn.f32x2 %0, %1, %2;" : "=l"(r) : "l"(a), "l"(b));
    return r;
}
__device__ __forceinline__ void unpack2(u64 v, float& lo, float& hi) {
    unsigned int l, h;
    asm("mov.b64 {%0, %1}, %2;" : "=r"(l), "=r"(h) : "l"(v));
    lo = __uint_as_float(l);
    hi = __uint_as_float(h);
}

// ---------------- degree / dinv ----------------
__global__ void k_zero_deg() {
    int i = blockIdx.x * blockDim.x + threadIdx.x;
    if (i < N_NODES) g_deg[i] = 0;
}
__global__ void k_count(const int* __restrict__ ei) {
    int i = blockIdx.x * blockDim.x + threadIdx.x;
    if (i < N_EDGES / 4) {
        int4 v = ((const int4*)ei)[i];
        atomicAdd(&g_deg[v.x], 1);
        atomicAdd(&g_deg[v.y], 1);
        atomicAdd(&g_deg[v.z], 1);
        atomicAdd(&g_deg[v.w], 1);
    }
}

// ---------------- scan (CSR rowptr over real-edge counts) ----------------
__global__ void __launch_bounds__(SCAN_B) k_scan1() {
    __shared__ int s[SCAN_B];
    int t = threadIdx.x;
    int i = blockIdx.x * SCAN_B + t;
    s[t] = (i < N_NODES) ? g_deg[i] : 0;
    __syncthreads();
#pragma unroll
    for (int off = 1; off < SCAN_B; off <<= 1) {
        int add = (t >= off) ? s[t - off] : 0;
        __syncthreads();
        s[t] += add;
        __syncthreads();
    }
    g_scan[i] = s[t];
    if (t == SCAN_B - 1) g_bsum[blockIdx.x] = s[t];
}
__global__ void k_scan2() {
    __shared__ int s[128];
    int t = threadIdx.x;
    s[t] = (t < SCAN_G) ? g_bsum[t] : 0;
    __syncthreads();
#pragma unroll
    for (int off = 1; off < 128; off <<= 1) {
        int add = (t >= off) ? s[t - off] : 0;
        __syncthreads();
        s[t] += add;
        __syncthreads();
    }
    if (t < SCAN_G) g_boff[t] = s[t] - g_bsum[t];  // exclusive
}
__global__ void __launch_bounds__(SCAN_B) k_scan3() {   // + dinv fused
    int i = blockIdx.x * SCAN_B + threadIdx.x;
    if (i < N_NODES) {
        int deg = g_deg[i];
        int incl = g_scan[i] + g_boff[blockIdx.x];
        g_rowptr[i + 1] = incl;
        g_cursor[i] = incl - deg;
        g_dinv[i] = rsqrtf((float)(deg + 1));   // +1 self loop
        if (i == 0) g_rowptr[0] = 0;
    }
}

// ---------------- scatter edges into CSR ----------------
__global__ void k_scatter(const int* __restrict__ ei) {
    int i = blockIdx.x * blockDim.x + threadIdx.x;
    if (i >= N_EDGES / 4) return;
    int4 r4 = ((const int4*)ei)[i];
    int4 c4 = ((const int4*)(ei + N_EDGES))[i];
#pragma unroll
    for (int k = 0; k < 4; k++) {
        int r = (k == 0) ? r4.x : (k == 1) ? r4.y : (k == 2) ? r4.z : r4.w;
        int c = (k == 0) ? c4.x : (k == 1) ? c4.y : (k == 2) ? c4.z : c4.w;
        int pos = atomicAdd(&g_cursor[r], 1);
        float w = g_dinv[r] * g_dinv[c];
        g_cw[pos] = make_int2(c, __float_as_int(w));
    }
}

// ---------------- GEMM1: h0 = x @ W1 (100000x512 @ 512x16), f32x2 ----------------
#define G1_ROWS 256
#define G1_KC   32
__global__ void __launch_bounds__(256) k_gemm1(const float* __restrict__ x,
                                               const float* __restrict__ W1) {
    __shared__ float xs[G1_ROWS][G1_KC + 1];   // stride 33: conflict-free
    __shared__ uint4 w1s[G1_KC * 4];           // 32 k x 16 cols (as 4x uint4)
    int tid = threadIdx.x;
    int row0 = blockIdx.x * G1_ROWS;
    int r = row0 + tid;

    u64 acc[8];                                 // col pairs (0,1)..(14,15)
#pragma unroll
    for (int c = 0; c < 8; c++) acc[c] = 0ull;

    int f4 = tid & 7, rbase = tid >> 3;
    for (int s = 0; s < 512 / G1_KC; s++) {
        if (tid < G1_KC * 4) w1s[tid] = ((const uint4*)W1)[s * G1_KC * 4 + tid];
        int rl = rbase;
#pragma unroll
        for (int i = 0; i < 8; i++, rl += 32) {
            int rr = row0 + rl;
            float4 v = make_float4(0.f, 0.f, 0.f, 0.f);
            if (rr < N_NODES) v = ((const float4*)(x + (size_t)rr * 512))[s * 8 + f4];
            xs[rl][f4 * 4 + 0] = v.x;
            xs[rl][f4 * 4 + 1] = v.y;
            xs[rl][f4 * 4 + 2] = v.z;
            xs[rl][f4 * 4 + 3] = v.w;
        }
        __syncthreads();
#pragma unroll
        for (int k = 0; k < G1_KC; k++) {
            u64 a2 = dup2(xs[tid][k]);
#pragma unroll
            for (int c2 = 0; c2 < 4; c2++) {
                uint4 w = w1s[k * 4 + c2];
                u64 wlo, whi;
                asm("mov.b64 %0, {%1, %2};" : "=l"(wlo) : "r"(w.x), "r"(w.y));
                asm("mov.b64 %0, {%1, %2};" : "=l"(whi) : "r"(w.z), "r"(w.w));
                ffma2(acc[c2 * 2 + 0], a2, wlo);
                ffma2(acc[c2 * 2 + 1], a2, whi);
            }
        }
        __syncthreads();
    }
    if (r < N_NODES) {
        ulonglong2* o = (ulonglong2*)(g_h0 + (size_t)r * 16);
#pragma unroll
        for (int i = 0; i < 4; i++)
            o[i] = make_ulonglong2(acc[2 * i], acc[2 * i + 1]);
    }
}

// ---------------- gather SpMM (16-wide): 1 thread per row, f32x2 ----------------
// STAGE 1: g_r1 = relu(spmm(g_h0) + b1);  STAGE 2: g_t = spmm(g_r1)
template <int STAGE>
__global__ void k_gather(const float* __restrict__ bias) {
    const float* __restrict__ src = (STAGE == 1) ? g_h0 : g_r1;
    float* __restrict__       dst = (STAGE == 1) ? g_r1 : g_t;
    int r = blockIdx.x * blockDim.x + threadIdx.x;
    if (r >= N_NODES) return;

    float d = g_dinv[r];
    u64 dd2 = dup2(d * d);
    const ulonglong2* s2 = (const ulonglong2*)src;

    u64 acc[8];
    {   // self-loop init: acc = dd * src[r]
        const ulonglong2* me = s2 + (size_t)r * 4;
#pragma unroll
        for (int i = 0; i < 4; i++) {
            ulonglong2 v = me[i];
            acc[2 * i + 0] = mul2(dd2, v.x);
            acc[2 * i + 1] = mul2(dd2, v.y);
        }
    }

    int e = g_rowptr[r], e1 = g_rowptr[r + 1];
#pragma unroll 2
    for (; e < e1; e++) {
        int2 cw = g_cw[e];
        u64 w2 = dup2(__int_as_float(cw.y));
        const ulonglong2* h = s2 + (size_t)cw.x * 4;
        ulonglong2 h0 = h[0], h1 = h[1], h2 = h[2], h3 = h[3];
        ffma2(acc[0], w2, h0.x);
        ffma2(acc[1], w2, h0.y);
        ffma2(acc[2], w2, h1.x);
        ffma2(acc[3], w2, h1.y);
        ffma2(acc[4], w2, h2.x);
        ffma2(acc[5], w2, h2.y);
        ffma2(acc[6], w2, h3.x);
        ffma2(acc[7], w2, h3.y);
    }

    if (STAGE == 1) {
        float out[16];
#pragma unroll
        for (int i = 0; i < 8; i++) unpack2(acc[i], out[2 * i], out[2 * i + 1]);
#pragma unroll
        for (int j = 0; j < 16; j++) out[j] = fmaxf(out[j] + bias[j], 0.f);
        float4* o = (float4*)(dst + (size_t)r * 16);
#pragma unroll
        for (int j4 = 0; j4 < 4; j4++)
            o[j4] = make_float4(out[j4 * 4], out[j4 * 4 + 1], out[j4 * 4 + 2], out[j4 * 4 + 3]);
    } else {
        ulonglong2* o = (ulonglong2*)(dst + (size_t)r * 16);
#pragma unroll
        for (int i = 0; i < 4; i++)
            o[i] = make_ulonglong2(acc[2 * i], acc[2 * i + 1]);
    }
}

// ---------------- fused GEMM2 + bias + log_softmax ----------------
__global__ void __launch_bounds__(256) k_gemm2lsm(const float* __restrict__ W2,
                                                  const float* __restrict__ b2,
                                                  float* __restrict__ out) {
    __shared__ float4 w2s[160];   // 16 x 40
    __shared__ float  b2s[40];
    for (int i = threadIdx.x; i < 160; i += 256) w2s[i] = ((const float4*)W2)[i];
    if (threadIdx.x < 40) b2s[threadIdx.x] = b2[threadIdx.x];
    __syncthreads();

    int r = blockIdx.x * blockDim.x + threadIdx.x;
    if (r >= N_NODES) return;

    float tv[16];
    const float4* tp = (const float4*)(g_t + (size_t)r * 16);
#pragma unroll
    for (int k4 = 0; k4 < 4; k4++) {
        float4 v = tp[k4];
        tv[k4 * 4 + 0] = v.x; tv[k4 * 4 + 1] = v.y;
        tv[k4 * 4 + 2] = v.z; tv[k4 * 4 + 3] = v.w;
    }

    float acc[40];
#pragma unroll
    for (int j = 0; j < 40; j++) acc[j] = b2s[j];
#pragma unroll
    for (int k = 0; k < 16; k++) {
        float a = tv[k];
#pragma unroll
        for (int j4 = 0; j4 < 10; j4++) {
            float4 w = w2s[k * 10 + j4];
            acc[j4 * 4 + 0] += a * w.x;
            acc[j4 * 4 + 1] += a * w.y;
            acc[j4 * 4 + 2] += a * w.z;
            acc[j4 * 4 + 3] += a * w.w;
        }
    }
    float m = acc[0];
#pragma unroll
    for (int j = 1; j < 40; j++) m = fmaxf(m, acc[j]);
    float s = 0.f;
#pragma unroll
    for (int j = 0; j < 40; j++) s += expf(acc[j] - m);
    float L = m + logf(s);
    float4* o = (float4*)(out + (size_t)r * 40);
#pragma unroll
    for (int j4 = 0; j4 < 10; j4++)
        o[j4] = make_float4(acc[j4 * 4] - L, acc[j4 * 4 + 1] - L,
                            acc[j4 * 4 + 2] - L, acc[j4 * 4 + 3] - L);
}

// ---------------- launch ----------------
extern "C" void kernel_launch(void* const* d_in, const int* in_sizes, int n_in,
                              void* d_out, int out_size) {
    const float* x  = (const float*)d_in[0];
    const float* W1 = (const float*)d_in[1];
    const float* b1 = (const float*)d_in[2];
    const float* W2 = (const float*)d_in[3];
    const float* b2 = (const float*)d_in[4];
    const int*   ei = (const int*)d_in[5];
    float* out = (float*)d_out;

    k_zero_deg<<<(N_NODES + 255) / 256, 256>>>();
    k_count<<<(N_EDGES / 4 + 255) / 256, 256>>>(ei);

    k_scan1<<<SCAN_G, SCAN_B>>>();
    k_scan2<<<1, 128>>>();
    k_scan3<<<SCAN_G, SCAN_B>>>();
    k_scatter<<<(N_EDGES / 4 + 255) / 256, 256>>>(ei);

    k_gemm1<<<(N_NODES + G1_ROWS - 1) / G1_ROWS, 256>>>(x, W1);

    k_gather<1><<<(N_NODES + 255) / 256, 256>>>(b1);
    k_gather<2><<<(N_NODES + 255) / 256, 256>>>(b1);

    k_gemm2lsm<<<(N_NODES + 255) / 256, 256>>>(W2, b2, out);
}

// round 14
// speedup vs baseline: 1.3943x; 1.3932x over previous
#include <cuda_runtime.h>
#include <math.h>

#define N_NODES 100000
#define N_EDGES 3200000
#define SCAN_B 1024
#define SCAN_G 98            // 98*1024 = 100352 >= N_NODES

// ---------------- scratch (__device__ globals; no allocs) ----------------
__device__ int   g_deg[N_NODES];
__device__ float g_dinv[N_NODES];
__device__ int   g_rowptr[N_NODES + 1];
__device__ int   g_cursor[N_NODES];
__device__ int   g_scan[SCAN_G * SCAN_B];
__device__ int   g_bsum[SCAN_G];
__device__ int   g_boff[SCAN_G];
__device__ int2  g_cw[N_EDGES];           // packed (col, w-bits)
__device__ float g_h0[N_NODES * 16];      // x @ W1
__device__ float g_r1[N_NODES * 16];      // relu(spmm1 + b1)
__device__ float g_t [N_NODES * 16];      // spmm2(r1)

// ---------------- degree ----------------
__global__ void k_zero_deg() {
    int i = blockIdx.x * blockDim.x + threadIdx.x;
    if (i < N_NODES) g_deg[i] = 0;
}
__global__ void k_count(const int* __restrict__ ei) {
    int i = blockIdx.x * blockDim.x + threadIdx.x;
    if (i < N_EDGES / 4) {
        int4 v = ((const int4*)ei)[i];
        atomicAdd(&g_deg[v.x], 1);
        atomicAdd(&g_deg[v.y], 1);
        atomicAdd(&g_deg[v.z], 1);
        atomicAdd(&g_deg[v.w], 1);
    }
}

// ---------------- scan (CSR rowptr over real-edge counts) ----------------
__global__ void __launch_bounds__(SCAN_B) k_scan1() {
    __shared__ int s[SCAN_B];
    int t = threadIdx.x;
    int i = blockIdx.x * SCAN_B + t;
    s[t] = (i < N_NODES) ? g_deg[i] : 0;
    __syncthreads();
#pragma unroll
    for (int off = 1; off < SCAN_B; off <<= 1) {
        int add = (t >= off) ? s[t - off] : 0;
        __syncthreads();
        s[t] += add;
        __syncthreads();
    }
    g_scan[i] = s[t];
    if (t == SCAN_B - 1) g_bsum[blockIdx.x] = s[t];
}
__global__ void k_scan2() {
    __shared__ int s[128];
    int t = threadIdx.x;
    s[t] = (t < SCAN_G) ? g_bsum[t] : 0;
    __syncthreads();
#pragma unroll
    for (int off = 1; off < 128; off <<= 1) {
        int add = (t >= off) ? s[t - off] : 0;
        __syncthreads();
        s[t] += add;
        __syncthreads();
    }
    if (t < SCAN_G) g_boff[t] = s[t] - g_bsum[t];  // exclusive
}
__global__ void __launch_bounds__(SCAN_B) k_scan3() {   // + dinv fused
    int i = blockIdx.x * SCAN_B + threadIdx.x;
    if (i < N_NODES) {
        int deg = g_deg[i];
        int incl = g_scan[i] + g_boff[blockIdx.x];
        g_rowptr[i + 1] = incl;
        g_cursor[i] = incl - deg;
        g_dinv[i] = rsqrtf((float)(deg + 1));   // +1 self loop
        if (i == 0) g_rowptr[0] = 0;
    }
}

// ---------------- scatter edges into CSR ----------------
__global__ void k_scatter(const int* __restrict__ ei) {
    int i = blockIdx.x * blockDim.x + threadIdx.x;
    if (i >= N_EDGES / 4) return;
    int4 r4 = ((const int4*)ei)[i];
    int4 c4 = ((const int4*)(ei + N_EDGES))[i];
#pragma unroll
    for (int k = 0; k < 4; k++) {
        int r = (k == 0) ? r4.x : (k == 1) ? r4.y : (k == 2) ? r4.z : r4.w;
        int c = (k == 0) ? c4.x : (k == 1) ? c4.y : (k == 2) ? c4.z : c4.w;
        int pos = atomicAdd(&g_cursor[r], 1);
        float w = g_dinv[r] * g_dinv[c];
        g_cw[pos] = make_int2(c, __float_as_int(w));
    }
}

// ---------------- GEMM1: h0 = x @ W1 (100000x512 @ 512x16) ----------------
// block 256 threads = 256 rows; K staged in chunks of 32 through smem. (known-good)
#define G1_ROWS 256
#define G1_KC   32
__global__ void __launch_bounds__(256) k_gemm1(const float* __restrict__ x,
                                               const float* __restrict__ W1) {
    __shared__ float  xs[G1_ROWS][G1_KC + 1];   // stride 33: conflict-free
    __shared__ float4 w1s[G1_KC * 4];           // 32 k x 16 cols
    int tid = threadIdx.x;
    int row0 = blockIdx.x * G1_ROWS;
    int r = row0 + tid;

    float acc[16];
#pragma unroll
    for (int c = 0; c < 16; c++) acc[c] = 0.f;

    int f4 = tid & 7, rbase = tid >> 3;
    for (int s = 0; s < 512 / G1_KC; s++) {
        if (tid < G1_KC * 4) w1s[tid] = ((const float4*)W1)[s * G1_KC * 4 + tid];
        int rl = rbase;
#pragma unroll
        for (int i = 0; i < 8; i++, rl += 32) {
            int rr = row0 + rl;
            float4 v = make_float4(0.f, 0.f, 0.f, 0.f);
            if (rr < N_NODES) v = ((const float4*)(x + (size_t)rr * 512))[s * 8 + f4];
            xs[rl][f4 * 4 + 0] = v.x;
            xs[rl][f4 * 4 + 1] = v.y;
            xs[rl][f4 * 4 + 2] = v.z;
            xs[rl][f4 * 4 + 3] = v.w;
        }
        __syncthreads();
#pragma unroll
        for (int k = 0; k < G1_KC; k++) {
            float a = xs[tid][k];
#pragma unroll
            for (int c4 = 0; c4 < 4; c4++) {
                float4 w = w1s[k * 4 + c4];
                acc[c4 * 4 + 0] += a * w.x;
                acc[c4 * 4 + 1] += a * w.y;
                acc[c4 * 4 + 2] += a * w.z;
                acc[c4 * 4 + 3] += a * w.w;
            }
        }
        __syncthreads();
    }
    if (r < N_NODES) {
        float4* o = (float4*)(g_h0 + (size_t)r * 16);
#pragma unroll
        for (int c4 = 0; c4 < 4; c4++)
            o[c4] = make_float4(acc[c4 * 4], acc[c4 * 4 + 1], acc[c4 * 4 + 2], acc[c4 * 4 + 3]);
    }
}

// ---------------- gather SpMM (16-wide): WARP per row, CSR-vector ----------------
// 32 lanes = 8 edge-slots x 4 chunks. No intra-warp divergence; 64B coalesced
// gathers; edge word broadcast across the 4 lanes of a slot.
// STAGE 1: g_r1 = relu(spmm(g_h0) + b1);  STAGE 2: g_t = spmm(g_r1)
template <int STAGE>
__global__ void __launch_bounds__(256) k_gather(const float* __restrict__ bias) {
    const float* __restrict__ src = (STAGE == 1) ? g_h0 : g_r1;
    float* __restrict__       dst = (STAGE == 1) ? g_r1 : g_t;

    int r    = (blockIdx.x * blockDim.x + threadIdx.x) >> 5;
    int lane = threadIdx.x & 31;
    if (r >= N_NODES) return;
    int slot = lane >> 2, j = lane & 3;

    const float4* s4 = (const float4*)src;
    float4 acc = make_float4(0.f, 0.f, 0.f, 0.f);

    int e1 = g_rowptr[r + 1];
    for (int e = g_rowptr[r] + slot; e < e1; e += 8) {
        int2 cw = g_cw[e];                      // broadcast within slot
        float w = __int_as_float(cw.y);
        float4 h = s4[(size_t)cw.x * 4 + j];    // 4 lanes -> 64B coalesced
        acc.x += w * h.x;
        acc.y += w * h.y;
        acc.z += w * h.z;
        acc.w += w * h.w;
    }

    // reduce across the 8 slots (lanes differing in bits 2..4)
#pragma unroll
    for (int off = 4; off <= 16; off <<= 1) {
        acc.x += __shfl_xor_sync(0xffffffffu, acc.x, off);
        acc.y += __shfl_xor_sync(0xffffffffu, acc.y, off);
        acc.z += __shfl_xor_sync(0xffffffffu, acc.z, off);
        acc.w += __shfl_xor_sync(0xffffffffu, acc.w, off);
    }

    if (slot == 0) {
        float d  = g_dinv[r];
        float dd = d * d;
        float4 v = s4[(size_t)r * 4 + j];       // self loop
        acc.x += dd * v.x;
        acc.y += dd * v.y;
        acc.z += dd * v.z;
        acc.w += dd * v.w;
        if (STAGE == 1) {
            float4 b = ((const float4*)bias)[j];
            acc.x = fmaxf(acc.x + b.x, 0.f);
            acc.y = fmaxf(acc.y + b.y, 0.f);
            acc.z = fmaxf(acc.z + b.z, 0.f);
            acc.w = fmaxf(acc.w + b.w, 0.f);
        }
        ((float4*)dst)[(size_t)r * 4 + j] = acc;
    }
}

// ---------------- fused GEMM2 + bias + log_softmax ----------------
__global__ void __launch_bounds__(256) k_gemm2lsm(const float* __restrict__ W2,
                                                  const float* __restrict__ b2,
                                                  float* __restrict__ out) {
    __shared__ float4 w2s[160];   // 16 x 40
    __shared__ float  b2s[40];
    for (int i = threadIdx.x; i < 160; i += 256) w2s[i] = ((const float4*)W2)[i];
    if (threadIdx.x < 40) b2s[threadIdx.x] = b2[threadIdx.x];
    __syncthreads();

    int r = blockIdx.x * blockDim.x + threadIdx.x;
    if (r >= N_NODES) return;

    float tv[16];
    const float4* tp = (const float4*)(g_t + (size_t)r * 16);
#pragma unroll
    for (int k4 = 0; k4 < 4; k4++) {
        float4 v = tp[k4];
        tv[k4 * 4 + 0] = v.x; tv[k4 * 4 + 1] = v.y;
        tv[k4 * 4 + 2] = v.z; tv[k4 * 4 + 3] = v.w;
    }

    float acc[40];
#pragma unroll
    for (int j = 0; j < 40; j++) acc[j] = b2s[j];
#pragma unroll
    for (int k = 0; k < 16; k++) {
        float a = tv[k];
#pragma unroll
        for (int j4 = 0; j4 < 10; j4++) {
            float4 w = w2s[k * 10 + j4];
            acc[j4 * 4 + 0] += a * w.x;
            acc[j4 * 4 + 1] += a * w.y;
            acc[j4 * 4 + 2] += a * w.z;
            acc[j4 * 4 + 3] += a * w.w;
        }
    }
    float m = acc[0];
#pragma unroll
    for (int j = 1; j < 40; j++) m = fmaxf(m, acc[j]);
    float s = 0.f;
#pragma unroll
    for (int j = 0; j < 40; j++) s += expf(acc[j] - m);
    float L = m + logf(s);
    float4* o = (float4*)(out + (size_t)r * 40);
#pragma unroll
    for (int j4 = 0; j4 < 10; j4++)
        o[j4] = make_float4(acc[j4 * 4] - L, acc[j4 * 4 + 1] - L,
                            acc[j4 * 4 + 2] - L, acc[j4 * 4 + 3] - L);
}

// ---------------- launch ----------------
extern "C" void kernel_launch(void* const* d_in, const int* in_sizes, int n_in,
                              void* d_out, int out_size) {
    const float* x  = (const float*)d_in[0];
    const float* W1 = (const float*)d_in[1];
    const float* b1 = (const float*)d_in[2];
    const float* W2 = (const float*)d_in[3];
    const float* b2 = (const float*)d_in[4];
    const int*   ei = (const int*)d_in[5];
    float* out = (float*)d_out;

    k_zero_deg<<<(N_NODES + 255) / 256, 256>>>();
    k_count<<<(N_EDGES / 4 + 255) / 256, 256>>>(ei);

    k_scan1<<<SCAN_G, SCAN_B>>>();
    k_scan2<<<1, 128>>>();
    k_scan3<<<SCAN_G, SCAN_B>>>();
    k_scatter<<<(N_EDGES / 4 + 255) / 256, 256>>>(ei);

    k_gemm1<<<(N_NODES + G1_ROWS - 1) / G1_ROWS, 256>>>(x, W1);

    // warp per row: 100000 warps = 3.2M threads / 256 per block
    k_gather<1><<<(N_NODES * 32 + 255) / 256, 256>>>(b1);
    k_gather<2><<<(N_NODES * 32 + 255) / 256, 256>>>(b1);

    k_gemm2lsm<<<(N_NODES + 255) / 256, 256>>>(W2, b2, out);
}

// round 15
// speedup vs baseline: 1.6460x; 1.1806x over previous
#include <cuda_runtime.h>
#include <math.h>

#define N_NODES 100000
#define N_EDGES 3200000
#define SCAN_B 1024
#define SCAN_G 98            // 98*1024 = 100352 >= N_NODES

// ---------------- scratch (__device__ globals; no allocs) ----------------
__device__ int   g_deg[N_NODES];
__device__ float g_dinv[N_NODES];
__device__ int   g_rowptr[N_NODES + 1];
__device__ int   g_cursor[N_NODES];
__device__ int   g_scan[SCAN_G * SCAN_B];
__device__ int   g_bsum[SCAN_G];
__device__ int   g_boff[SCAN_G];
__device__ int2  g_cw[N_EDGES];           // packed (col, w-bits)
__device__ float g_h0[N_NODES * 16];      // x @ W1
__device__ float g_r1[N_NODES * 16];      // relu(spmm1 + b1)
__device__ float g_t [N_NODES * 16];      // spmm2(r1)

// ---------------- degree / dinv ----------------
__global__ void k_zero_deg() {
    int i = blockIdx.x * blockDim.x + threadIdx.x;
    if (i < N_NODES) g_deg[i] = 0;
}
__global__ void k_count(const int* __restrict__ ei) {
    int e = blockIdx.x * blockDim.x + threadIdx.x;
    if (e < N_EDGES) atomicAdd(&g_deg[ei[e]], 1);
}
__global__ void k_dinv() {
    int i = blockIdx.x * blockDim.x + threadIdx.x;
    if (i < N_NODES) g_dinv[i] = rsqrtf((float)(g_deg[i] + 1));  // +1 self loop
}

// ---------------- scan (CSR rowptr over real-edge counts) ----------------
__global__ void __launch_bounds__(SCAN_B) k_scan1() {
    __shared__ int s[SCAN_B];
    int t = threadIdx.x;
    int i = blockIdx.x * SCAN_B + t;
    s[t] = (i < N_NODES) ? g_deg[i] : 0;
    __syncthreads();
#pragma unroll
    for (int off = 1; off < SCAN_B; off <<= 1) {
        int add = (t >= off) ? s[t - off] : 0;
        __syncthreads();
        s[t] += add;
        __syncthreads();
    }
    g_scan[i] = s[t];
    if (t == SCAN_B - 1) g_bsum[blockIdx.x] = s[t];
}
__global__ void k_scan2() {
    __shared__ int s[128];
    int t = threadIdx.x;
    s[t] = (t < SCAN_G) ? g_bsum[t] : 0;
    __syncthreads();
#pragma unroll
    for (int off = 1; off < 128; off <<= 1) {
        int add = (t >= off) ? s[t - off] : 0;
        __syncthreads();
        s[t] += add;
        __syncthreads();
    }
    if (t < SCAN_G) g_boff[t] = s[t] - g_bsum[t];  // exclusive
}
__global__ void __launch_bounds__(SCAN_B) k_scan3() {
    int i = blockIdx.x * SCAN_B + threadIdx.x;
    if (i < N_NODES) {
        int incl = g_scan[i] + g_boff[blockIdx.x];
        g_rowptr[i + 1] = incl;
        g_cursor[i] = incl - g_deg[i];
        if (i == 0) g_rowptr[0] = 0;
    }
}

// ---------------- scatter edges into CSR ----------------
__global__ void k_scatter(const int* __restrict__ ei) {
    int e = blockIdx.x * blockDim.x + threadIdx.x;
    if (e >= N_EDGES) return;
    int r = ei[e];
    int c = ei[e + N_EDGES];
    int pos = atomicAdd(&g_cursor[r], 1);
    float w = g_dinv[r] * g_dinv[c];
    g_cw[pos] = make_int2(c, __float_as_int(w));
}

// ---------------- GEMM1: h0 = x @ W1 (100000x512 @ 512x16) ----------------
// block 256 threads = 256 rows; K staged in chunks of 32 through smem. (known-good)
#define G1_ROWS 256
#define G1_KC   32
__global__ void __launch_bounds__(256) k_gemm1(const float* __restrict__ x,
                                               const float* __restrict__ W1) {
    __shared__ float  xs[G1_ROWS][G1_KC + 1];   // stride 33: conflict-free
    __shared__ float4 w1s[G1_KC * 4];           // 32 k x 16 cols
    int tid = threadIdx.x;
    int row0 = blockIdx.x * G1_ROWS;
    int r = row0 + tid;

    float acc[16];
#pragma unroll
    for (int c = 0; c < 16; c++) acc[c] = 0.f;

    int f4 = tid & 7, rbase = tid >> 3;
    for (int s = 0; s < 512 / G1_KC; s++) {
        if (tid < G1_KC * 4) w1s[tid] = ((const float4*)W1)[s * G1_KC * 4 + tid];
        int rl = rbase;
#pragma unroll
        for (int i = 0; i < 8; i++, rl += 32) {
            int rr = row0 + rl;
            float4 v = make_float4(0.f, 0.f, 0.f, 0.f);
            if (rr < N_NODES) v = ((const float4*)(x + (size_t)rr * 512))[s * 8 + f4];
            xs[rl][f4 * 4 + 0] = v.x;
            xs[rl][f4 * 4 + 1] = v.y;
            xs[rl][f4 * 4 + 2] = v.z;
            xs[rl][f4 * 4 + 3] = v.w;
        }
        __syncthreads();
#pragma unroll
        for (int k = 0; k < G1_KC; k++) {
            float a = xs[tid][k];
#pragma unroll
            for (int c4 = 0; c4 < 4; c4++) {
                float4 w = w1s[k * 4 + c4];
                acc[c4 * 4 + 0] += a * w.x;
                acc[c4 * 4 + 1] += a * w.y;
                acc[c4 * 4 + 2] += a * w.z;
                acc[c4 * 4 + 3] += a * w.w;
            }
        }
        __syncthreads();
    }
    if (r < N_NODES) {
        float4* o = (float4*)(g_h0 + (size_t)r * 16);
#pragma unroll
        for (int c4 = 0; c4 < 4; c4++)
            o[c4] = make_float4(acc[c4 * 4], acc[c4 * 4 + 1], acc[c4 * 4 + 2], acc[c4 * 4 + 3]);
    }
}

// ---------------- gather SpMM (16-wide): 4 threads per row (known-good) ----------------
// STAGE 1: g_r1 = relu(spmm(g_h0) + b1);  STAGE 2: g_t = spmm(g_r1)
template <int STAGE>
__global__ void k_gather(const float* __restrict__ bias) {
    const float* __restrict__ src = (STAGE == 1) ? g_h0 : g_r1;
    float* __restrict__       dst = (STAGE == 1) ? g_r1 : g_t;
    int t = blockIdx.x * blockDim.x + threadIdx.x;
    int r = t >> 2, j = t & 3;
    if (r >= N_NODES) return;
    float d = g_dinv[r];
    const float4* s4 = (const float4*)src;
    float4 v = s4[r * 4 + j];
    float dd = d * d;
    float4 acc = make_float4(dd * v.x, dd * v.y, dd * v.z, dd * v.w);
    int e = g_rowptr[r], e1 = g_rowptr[r + 1];
#pragma unroll 4
    for (; e < e1; e++) {
        int2 cw = g_cw[e];
        float w = __int_as_float(cw.y);
        float4 h = s4[cw.x * 4 + j];
        acc.x += w * h.x;
        acc.y += w * h.y;
        acc.z += w * h.z;
        acc.w += w * h.w;
    }
    if (STAGE == 1) {
        float4 b = ((const float4*)bias)[j];
        acc.x = fmaxf(acc.x + b.x, 0.f);
        acc.y = fmaxf(acc.y + b.y, 0.f);
        acc.z = fmaxf(acc.z + b.z, 0.f);
        acc.w = fmaxf(acc.w + b.w, 0.f);
    }
    ((float4*)dst)[r * 4 + j] = acc;
}

// ---------------- fused GEMM2 + bias + log_softmax ----------------
__global__ void __launch_bounds__(256) k_gemm2lsm(const float* __restrict__ W2,
                                                  const float* __restrict__ b2,
                                                  float* __restrict__ out) {
    __shared__ float4 w2s[160];   // 16 x 40
    __shared__ float  b2s[40];
    for (int i = threadIdx.x; i < 160; i += 256) w2s[i] = ((const float4*)W2)[i];
    if (threadIdx.x < 40) b2s[threadIdx.x] = b2[threadIdx.x];
    __syncthreads();

    int r = blockIdx.x * blockDim.x + threadIdx.x;
    if (r >= N_NODES) return;

    float tv[16];
    const float4* tp = (const float4*)(g_t + (size_t)r * 16);
#pragma unroll
    for (int k4 = 0; k4 < 4; k4++) {
        float4 v = tp[k4];
        tv[k4 * 4 + 0] = v.x; tv[k4 * 4 + 1] = v.y;
        tv[k4 * 4 + 2] = v.z; tv[k4 * 4 + 3] = v.w;
    }

    float acc[40];
#pragma unroll
    for (int j = 0; j < 40; j++) acc[j] = b2s[j];
#pragma unroll
    for (int k = 0; k < 16; k++) {
        float a = tv[k];
#pragma unroll
        for (int j4 = 0; j4 < 10; j4++) {
            float4 w = w2s[k * 10 + j4];
            acc[j4 * 4 + 0] += a * w.x;
            acc[j4 * 4 + 1] += a * w.y;
            acc[j4 * 4 + 2] += a * w.z;
            acc[j4 * 4 + 3] += a * w.w;
        }
    }
    float m = acc[0];
#pragma unroll
    for (int j = 1; j < 40; j++) m = fmaxf(m, acc[j]);
    float s = 0.f;
#pragma unroll
    for (int j = 0; j < 40; j++) s += expf(acc[j] - m);
    float L = m + logf(s);
    float4* o = (float4*)(out + (size_t)r * 40);
#pragma unroll
    for (int j4 = 0; j4 < 10; j4++)
        o[j4] = make_float4(acc[j4 * 4] - L, acc[j4 * 4 + 1] - L,
                            acc[j4 * 4 + 2] - L, acc[j4 * 4 + 3] - L);
}

// ---------------- launch: fork gemm1 onto a side stream, join before gather1 ----------------
extern "C" void kernel_launch(void* const* d_in, const int* in_sizes, int n_in,
                              void* d_out, int out_size) {
    const float* x  = (const float*)d_in[0];
    const float* W1 = (const float*)d_in[1];
    const float* b1 = (const float*)d_in[2];
    const float* W2 = (const float*)d_in[3];
    const float* b2 = (const float*)d_in[4];
    const int*   ei = (const int*)d_in[5];
    float* out = (float*)d_out;

    // One-time resource creation (happens on the pre-capture correctness call;
    // no device memory is allocated, and captured work is identical every call).
    static cudaStream_t s1 = nullptr;
    static cudaEvent_t  evFork = nullptr, evJoin = nullptr;
    if (!s1) {
        cudaStreamCreateWithFlags(&s1, cudaStreamNonBlocking);
        cudaEventCreateWithFlags(&evFork, cudaEventDisableTiming);
        cudaEventCreateWithFlags(&evJoin, cudaEventDisableTiming);
    }

    // Fork: chain A (gemm1) on side stream, concurrent with edge prep below.
    cudaEventRecord(evFork, 0);
    cudaStreamWaitEvent(s1, evFork, 0);
    k_gemm1<<<(N_NODES + G1_ROWS - 1) / G1_ROWS, 256, 0, s1>>>(x, W1);
    cudaEventRecord(evJoin, s1);

    // Chain B: degree -> dinv -> scan -> scatter (edge prep), on capture stream.
    k_zero_deg<<<(N_NODES + 255) / 256, 256>>>();
    k_count<<<(N_EDGES + 255) / 256, 256>>>(ei);
    k_dinv<<<(N_NODES + 255) / 256, 256>>>();
    k_scan1<<<SCAN_G, SCAN_B>>>();
    k_scan2<<<1, 128>>>();
    k_scan3<<<SCAN_G, SCAN_B>>>();
    k_scatter<<<(N_EDGES + 255) / 256, 256>>>(ei);

    // Join: gathers need both g_h0 (chain A) and CSR (chain B).
    cudaStreamWaitEvent(0, evJoin, 0);

    k_gather<1><<<(N_NODES * 4 + 255) / 256, 256>>>(b1);
    k_gather<2><<<(N_NODES * 4 + 255) / 256, 256>>>(b1);

    k_gemm2lsm<<<(N_NODES + 255) / 256, 256>>>(W2, b2, out);
}